// round 15
// baseline (speedup 1.0000x reference)
#include <cuda_runtime.h>
#include <cuda_bf16.h>
#include <math.h>
#include <stdint.h>

// Problem constants
#define S 2048
#define H 2048
#define NH 16
#define HD 128
#define QKV_N (3 * H)         // 6144
#define MIXED_W (3 * HD * NH) // 6144
#define HEAD_W (3 * HD)       // 384

// Scratch
__device__ float g_mixed[(size_t)S * QKV_N];
__device__ float g_ctx[(size_t)S * H];
__device__ float g_hidden_t[(size_t)S * H];
__device__ float g_wqkv_t[(size_t)QKV_N * H];
__device__ float g_wdense_t[(size_t)H * H];

// ---------------------------------------------------------------------------
// Helpers
// ---------------------------------------------------------------------------
__device__ __forceinline__ uint32_t smem_to_u32(const void* p) {
    uint32_t a;
    asm("{ .reg .u64 t; cvta.to.shared.u64 t, %1; cvt.u32.u64 %0, t; }" : "=r"(a) : "l"(p));
    return a;
}
__device__ __forceinline__ uint32_t f32_to_tf32(float f) {
    uint32_t r;
    asm("cvt.rna.tf32.f32 %0, %1;" : "=r"(r) : "f"(f));
    return r;
}
__device__ __forceinline__ float tf32_round(float f) {
    return __uint_as_float(f32_to_tf32(f));
}
#define CP_ASYNC16(dst, src) \
    asm volatile("cp.async.cg.shared.global [%0], [%1], 16;" :: "r"(dst), "l"(src) : "memory")
#define CP_ASYNC_COMMIT() asm volatile("cp.async.commit_group;" ::: "memory")
#define CP_ASYNC_WAIT(n)  asm volatile("cp.async.wait_group %0;" :: "n"(n) : "memory")

__device__ __forceinline__ void mma_tf32(
    float c[4], const uint32_t a[4], const uint32_t b[2])
{
    asm volatile(
        "mma.sync.aligned.m16n8k8.row.col.f32.tf32.tf32.f32 "
        "{%0,%1,%2,%3}, {%4,%5,%6,%7}, {%8,%9}, {%0,%1,%2,%3};"
        : "+f"(c[0]), "+f"(c[1]), "+f"(c[2]), "+f"(c[3])
        : "r"(a[0]), "r"(a[1]), "r"(a[2]), "r"(a[3]), "r"(b[0]), "r"(b[1]));
}
__device__ __forceinline__ uint32_t f4c(const float4& v, int j) {
    const float* p = (const float*)&v;
    return __float_as_uint(p[j]);
}

// ---------------------------------------------------------------------------
// Fused tf32 pre-round of all three GEMM operand tensors (one launch)
// ---------------------------------------------------------------------------
#define N4_HID ((S * H) / 4)
#define N4_WQKV ((QKV_N * H) / 4)
#define N4_WD ((H * H) / 4)
#define N4_TOT (N4_HID + N4_WQKV + N4_WD)

__global__ void round_all_kernel(const float4* __restrict__ hid,
                                 const float4* __restrict__ wq,
                                 const float4* __restrict__ wd,
                                 float4* __restrict__ hid_o,
                                 float4* __restrict__ wq_o,
                                 float4* __restrict__ wd_o)
{
    for (int i = blockIdx.x * blockDim.x + threadIdx.x; i < N4_TOT;
         i += gridDim.x * blockDim.x) {
        const float4* src;
        float4* dst;
        int j = i;
        if (j < N4_HID) { src = hid; dst = hid_o; }
        else if (j < N4_HID + N4_WQKV) { j -= N4_HID; src = wq; dst = wq_o; }
        else { j -= N4_HID + N4_WQKV; src = wd; dst = wd_o; }
        float4 v = src[j];
        v.x = tf32_round(v.x); v.y = tf32_round(v.y);
        v.z = tf32_round(v.z); v.w = tf32_round(v.w);
        dst[j] = v;
    }
}

// ---------------------------------------------------------------------------
// tf32 mma.sync GEMM: C[M,N] = A[M,K]*B[N,K]^T (+bias)
// Pre-rounded inputs -> no cvt. BM=BN=128, BK=32, 256 threads
// (8 warps, 2x4 of 64x32 warp tiles). 3-stage cp.async pipeline, ONE barrier
// per k-chunk; next-next chunk's loads issued BEFORE the compute block.
// Last iteration uses WAIT(0) (race fix, see R13 post-mortem).
// ---------------------------------------------------------------------------
#define TSTR 36
#define TILE_WORDS (128 * TSTR)                  // 4608
#define GT_SMEM_BYTES (6 * TILE_WORDS * 4)       // 110592

__global__ __launch_bounds__(256) void gemm_tc_kernel(
    const float* __restrict__ A, const float* __restrict__ B,
    const float* __restrict__ bias, float* __restrict__ C,
    int M, int N, int K)
{
    extern __shared__ float smf[];
    const uint32_t smem_base = smem_to_u32(smf);
    const int tid  = threadIdx.x;
    const int wid  = tid >> 5;
    const int lane = tid & 31;
    const int wm = wid >> 2;         // 0..1
    const int wn = wid & 3;          // 0..3
    const int bm = blockIdx.y * 128;
    const int bn = blockIdx.x * 128;

    const int lr = lane >> 2;
    const int lc = lane & 3;

    const int ld_row = tid >> 3;         // 0..31
    const int ld_k4  = (tid & 7) << 2;

    float c[4][4][4];
#pragma unroll
    for (int mt = 0; mt < 4; mt++)
#pragma unroll
        for (int nt = 0; nt < 4; nt++)
#pragma unroll
            for (int r = 0; r < 4; r++) c[mt][nt][r] = 0.f;

    const int NK = K >> 5;

    auto load_tiles = [&](int i) {
        const int st = i % 3;
        const int k0 = i << 5;
        const uint32_t abase = smem_base + (uint32_t)(st * 2 * TILE_WORDS) * 4;
        const uint32_t bbase = abase + TILE_WORDS * 4;
#pragma unroll
        for (int j = 0; j < 4; j++) {
            const int m = ld_row + 32 * j;
            const uint32_t soff = (uint32_t)(m * TSTR + ld_k4) * 4;
            CP_ASYNC16(abase + soff, A + (size_t)(bm + m) * K + k0 + ld_k4);
            CP_ASYNC16(bbase + soff, B + (size_t)(bn + m) * K + k0 + ld_k4);
        }
        CP_ASYNC_COMMIT();
    };

    load_tiles(0);
    load_tiles(1);

    for (int i = 0; i < NK; i++) {
        if (i + 1 < NK) { CP_ASYNC_WAIT(1); }   // newest group (i+1) may stay pending
        else            { CP_ASYNC_WAIT(0); }   // last iter: drain (group i is newest)
        __syncthreads();

        // Issue next-next chunk's loads early (writes stage (i-1)%3, whose
        // readers all passed the barrier above).
        if (i + 2 < NK) load_tiles(i + 2);

        const float* As = smf + (size_t)(i % 3) * 2 * TILE_WORDS;
        const float* Bs = As + TILE_WORDS;

#pragma unroll
        for (int ks = 0; ks < 4; ks++) {
            const int kc = ks * 8 + lc;
            uint32_t af[4][4];
#pragma unroll
            for (int mt = 0; mt < 4; mt++) {
                const int row = wm * 64 + mt * 16 + lr;
                af[mt][0] = __float_as_uint(As[row * TSTR + kc]);
                af[mt][1] = __float_as_uint(As[(row + 8) * TSTR + kc]);
                af[mt][2] = __float_as_uint(As[row * TSTR + kc + 4]);
                af[mt][3] = __float_as_uint(As[(row + 8) * TSTR + kc + 4]);
            }
            uint32_t bf[4][2];
#pragma unroll
            for (int nt = 0; nt < 4; nt++) {
                const int ncol = wn * 32 + nt * 8 + lr;
                bf[nt][0] = __float_as_uint(Bs[ncol * TSTR + kc]);
                bf[nt][1] = __float_as_uint(Bs[ncol * TSTR + kc + 4]);
            }
#pragma unroll
            for (int mt = 0; mt < 4; mt++)
#pragma unroll
                for (int nt = 0; nt < 4; nt++)
                    mma_tf32(c[mt][nt], af[mt], bf[nt]);
        }
    }

#pragma unroll
    for (int nt = 0; nt < 4; nt++) {
        const int col = bn + wn * 32 + nt * 8 + lc * 2;
        float b0 = 0.f, b1 = 0.f;
        if (bias) { b0 = bias[col]; b1 = bias[col + 1]; }
#pragma unroll
        for (int mt = 0; mt < 4; mt++) {
            const int row = bm + wm * 64 + mt * 16 + lr;
            float2 v0 = make_float2(c[mt][nt][0] + b0, c[mt][nt][1] + b1);
            float2 v1 = make_float2(c[mt][nt][2] + b0, c[mt][nt][3] + b1);
            *(float2*)(C + (size_t)row * N + col) = v0;
            *(float2*)(C + (size_t)(row + 8) * N + col) = v1;
        }
    }
}

// ---------------------------------------------------------------------------
// Rotary embedding + tf32 pre-round + q pre-scale
// ---------------------------------------------------------------------------
__global__ void rotary_kernel(float* __restrict__ mixed)
{
    const int s = blockIdx.x;
    const int n = blockIdx.y;
    const int d = threadIdx.x;  // 0..63
    const float inv_freq = expf(-(float)d * (9.210340371976184f / 64.0f));
    const float freq = (float)s * inv_freq;
    float si, c;
    sincosf(freq, &si, &c);
    const float scale = 0.08838834764831845f;

    float* base = mixed + (size_t)s * MIXED_W + n * HEAD_W;
    {
        float* p = base;
        const float x1 = p[d];
        const float x2 = p[d + 64];
        p[d]      = tf32_round(scale * (x1 * c - x2 * si));
        p[d + 64] = tf32_round(scale * (x2 * c + x1 * si));
    }
    {
        float* p = base + HD;
        const float x1 = p[d];
        const float x2 = p[d + 64];
        p[d]      = tf32_round(x1 * c - x2 * si);
        p[d + 64] = tf32_round(x2 * c + x1 * si);
    }
    {
        float* p = base + 2 * HD;
        p[d]      = tf32_round(p[d]);
        p[d + 64] = tf32_round(p[d + 64]);
    }
}

// ---------------------------------------------------------------------------
// tf32 mma.sync flash attention (causal)
// AQ=64, AK=64, SINGLE KV buffer, 128 threads (4 warps x 16 q-rows),
// 2 CTAs/SM (smem 108.5 KB). Cross-CTA overlap replaces intra-CTA
// double-buffering. 1-D grid, qt-major descending.
// ---------------------------------------------------------------------------
#define AQ 64
#define AK 64
#define QST 144
#define QST4 (QST / 4)
#define VST 136
#define QWRD (AQ * QST)             // 9216
#define KWRD (AK * QST)             // 9216
#define VWRD (AK * VST)             // 8704
#define ATTN_SMEM_BYTES ((QWRD + KWRD + VWRD) * 4)  // 108544 B
#define NQT (S / AQ)   // 32

__global__ __launch_bounds__(128, 2) void attn_tc_kernel(
    const float* __restrict__ mixed, float* __restrict__ ctx)
{
    extern __shared__ float sf[];
    const uint32_t smem_base = smem_to_u32(sf);

    const int tid  = threadIdx.x;
    const int wid  = tid >> 5;       // 0..3
    const int lane = tid & 31;
    const int lr = lane >> 2;
    const int lc = lane & 3;
    const int bid = blockIdx.x;
    const int h  = bid & (NH - 1);
    const int qt = NQT - 1 - (bid >> 4);   // qt-major, biggest first
    const int r0 = qt * AQ;
    const int m0 = wid * 16;
    const size_t hoff = (size_t)h * HEAD_W;

    auto load_kv = [&](int kt) {
        const uint32_t kb = smem_base + (uint32_t)QWRD * 4;
        const uint32_t vb = kb + KWRD * 4;
        const float* kg = mixed + (size_t)(kt * AK) * MIXED_W + hoff + HD;
        const float* vg = kg + HD;
#pragma unroll
        for (int it = 0; it < 16; it++) {
            const int u = tid + (it << 7);           // 0..2047
            const int row = u >> 5, c4 = (u & 31) << 2;
            CP_ASYNC16(kb + (uint32_t)(row * QST + c4) * 4, kg + (size_t)row * MIXED_W + c4);
            CP_ASYNC16(vb + (uint32_t)(row * VST + c4) * 4, vg + (size_t)row * MIXED_W + c4);
        }
        CP_ASYNC_COMMIT();
    };

    // stage Q (pre-scaled + pre-rounded by rotary) and first KV tile
    {
        const float* qg = mixed + (size_t)r0 * MIXED_W + hoff;
#pragma unroll
        for (int it = 0; it < 16; it++) {
            const int u = tid + (it << 7);
            const int row = u >> 5, c4 = (u & 31) << 2;
            CP_ASYNC16(smem_base + (uint32_t)(row * QST + c4) * 4,
                       qg + (size_t)row * MIXED_W + c4);
        }
        CP_ASYNC_COMMIT();
    }
    load_kv(0);

    const int nkt = qt + 1;

    float co[16][4];
#pragma unroll
    for (int nt = 0; nt < 16; nt++)
#pragma unroll
        for (int r = 0; r < 4; r++) co[nt][r] = 0.f;
    float mrow[2] = {-1e30f, -1e30f};
    float lrow[2] = {0.f, 0.f};

    const int src1 = (lane & ~3) | (lc >> 1);
    const int src2 = src1 + 2;
    const bool podd = (lc & 1);

    const float* Ks = sf + QWRD;
    const float* Vs = Ks + KWRD;
    const float4* Qs4 = (const float4*)sf;
    const float4* Ks4 = (const float4*)Ks;

    for (int kt = 0; kt < nkt; kt++) {
        CP_ASYNC_WAIT(0);
        __syncthreads();   // KV(kt) (and Q on first iter) visible to all

        const int c0 = kt * AK;

        // ---- S = Q K^T (permuted-k LDS.128 fragments) ----
        float s[8][4];
#pragma unroll
        for (int nt = 0; nt < 8; nt++)
#pragma unroll
            for (int r = 0; r < 4; r++) s[nt][r] = 0.f;

#pragma unroll
        for (int ch = 0; ch < 4; ch++) {
            const int cb = ch * 8;
            const int row = m0 + lr;
            float4 qa[2][2];
            qa[0][0] = Qs4[row * QST4 + cb + lc];
            qa[0][1] = Qs4[row * QST4 + cb + 4 + lc];
            qa[1][0] = Qs4[(row + 8) * QST4 + cb + lc];
            qa[1][1] = Qs4[(row + 8) * QST4 + cb + 4 + lc];
#pragma unroll
            for (int g = 0; g < 2; g++) {
                float4 kb4[4][2];
#pragma unroll
                for (int q = 0; q < 4; q++) {
                    const int col = (g * 4 + q) * 8 + lr;
                    kb4[q][0] = Ks4[col * QST4 + cb + lc];
                    kb4[q][1] = Ks4[col * QST4 + cb + 4 + lc];
                }
#pragma unroll
                for (int j = 0; j < 4; j++) {
                    uint32_t a[4] = { f4c(qa[0][0], j), f4c(qa[1][0], j),
                                      f4c(qa[0][1], j), f4c(qa[1][1], j) };
#pragma unroll
                    for (int q = 0; q < 4; q++) {
                        uint32_t b[2] = { f4c(kb4[q][0], j), f4c(kb4[q][1], j) };
                        mma_tf32(s[g * 4 + q], a, b);
                    }
                }
            }
        }

        // ---- causal mask (diagonal tile only) ----
        if (c0 + AK - 1 > r0 + m0) {
            const int rga = r0 + m0 + lr;
            const int rgb = rga + 8;
#pragma unroll
            for (int nt = 0; nt < 8; nt++) {
                const int cg0 = c0 + nt * 8 + lc * 2;
                const int cg1 = cg0 + 1;
                if (cg0 > rga) s[nt][0] = -1e30f;
                if (cg1 > rga) s[nt][1] = -1e30f;
                if (cg0 > rgb) s[nt][2] = -1e30f;
                if (cg1 > rgb) s[nt][3] = -1e30f;
            }
        }

        // ---- online softmax ----
#pragma unroll
        for (int hh = 0; hh < 2; hh++) {
            float mx = -1e30f;
#pragma unroll
            for (int nt = 0; nt < 8; nt++)
                mx = fmaxf(mx, fmaxf(s[nt][2 * hh], s[nt][2 * hh + 1]));
            mx = fmaxf(mx, __shfl_xor_sync(0xffffffffu, mx, 1));
            mx = fmaxf(mx, __shfl_xor_sync(0xffffffffu, mx, 2));
            const float m_new = fmaxf(mrow[hh], mx);
            const float sc = __expf(mrow[hh] - m_new);
            float rs = 0.f;
#pragma unroll
            for (int nt = 0; nt < 8; nt++) {
                const float p0 = __expf(s[nt][2 * hh] - m_new);
                const float p1 = __expf(s[nt][2 * hh + 1] - m_new);
                s[nt][2 * hh] = p0;
                s[nt][2 * hh + 1] = p1;
                rs += p0 + p1;
            }
            rs += __shfl_xor_sync(0xffffffffu, rs, 1);
            rs += __shfl_xor_sync(0xffffffffu, rs, 2);
            lrow[hh] = lrow[hh] * sc + rs;
            mrow[hh] = m_new;
#pragma unroll
            for (int nt = 0; nt < 16; nt++) {
                co[nt][2 * hh]     *= sc;
                co[nt][2 * hh + 1] *= sc;
            }
        }

        // ---- O += P V ----
#pragma unroll
        for (int kg = 0; kg < 8; kg++) {
            uint32_t pa[4];
            {
                const float x0 = __shfl_sync(0xffffffffu, s[kg][0], src1);
                const float x1 = __shfl_sync(0xffffffffu, s[kg][1], src1);
                pa[0] = f32_to_tf32(podd ? x1 : x0);
                const float x2 = __shfl_sync(0xffffffffu, s[kg][2], src1);
                const float x3 = __shfl_sync(0xffffffffu, s[kg][3], src1);
                pa[1] = f32_to_tf32(podd ? x3 : x2);
                const float y0 = __shfl_sync(0xffffffffu, s[kg][0], src2);
                const float y1 = __shfl_sync(0xffffffffu, s[kg][1], src2);
                pa[2] = f32_to_tf32(podd ? y1 : y0);
                const float y2 = __shfl_sync(0xffffffffu, s[kg][2], src2);
                const float y3 = __shfl_sync(0xffffffffu, s[kg][3], src2);
                pa[3] = f32_to_tf32(podd ? y3 : y2);
            }
#pragma unroll
            for (int nt = 0; nt < 16; nt++) {
                uint32_t vb[2];
                vb[0] = __float_as_uint(Vs[(kg * 8 + lc) * VST + nt * 8 + lr]);
                vb[1] = __float_as_uint(Vs[(kg * 8 + lc + 4) * VST + nt * 8 + lr]);
                mma_tf32(co[nt], pa, vb);
            }
        }

        __syncthreads();   // all warps done reading KV(kt)
        if (kt + 1 < nkt) load_kv(kt + 1);
    }

    // ---- normalize + store (tf32-rounded for dense GEMM) ----
    {
        const float li0 = 1.f / lrow[0];
        const float li1 = 1.f / lrow[1];
        const int row = r0 + m0 + lr;
#pragma unroll
        for (int nt = 0; nt < 16; nt++) {
            const int col = h * HD + nt * 8 + lc * 2;
            *(float2*)(ctx + (size_t)row * H + col) =
                make_float2(tf32_round(co[nt][0] * li0), tf32_round(co[nt][1] * li0));
            *(float2*)(ctx + (size_t)(row + 8) * H + col) =
                make_float2(tf32_round(co[nt][2] * li1), tf32_round(co[nt][3] * li1));
        }
    }
}

// ---------------------------------------------------------------------------
// Launch
// ---------------------------------------------------------------------------
extern "C" void kernel_launch(void* const* d_in, const int* in_sizes, int n_in,
                              void* d_out, int out_size)
{
    const float* hidden  = (const float*)d_in[0];
    const float* w_qkv   = (const float*)d_in[2];
    const float* b_qkv   = (const float*)d_in[3];
    const float* w_dense = (const float*)d_in[4];
    float* out = (float*)d_out;

    float *mixed, *ctx, *hidden_t, *wqkv_t, *wdense_t;
    cudaGetSymbolAddress((void**)&mixed, g_mixed);
    cudaGetSymbolAddress((void**)&ctx, g_ctx);
    cudaGetSymbolAddress((void**)&hidden_t, g_hidden_t);
    cudaGetSymbolAddress((void**)&wqkv_t, g_wqkv_t);
    cudaGetSymbolAddress((void**)&wdense_t, g_wdense_t);

    cudaFuncSetAttribute(gemm_tc_kernel,
                         cudaFuncAttributeMaxDynamicSharedMemorySize, GT_SMEM_BYTES);
    cudaFuncSetAttribute(attn_tc_kernel,
                         cudaFuncAttributeMaxDynamicSharedMemorySize, ATTN_SMEM_BYTES);

    // 0) fused tf32 pre-round of all GEMM operands (one launch)
    round_all_kernel<<<2048, 256>>>((const float4*)hidden, (const float4*)w_qkv,
                                    (const float4*)w_dense, (float4*)hidden_t,
                                    (float4*)wqkv_t, (float4*)wdense_t);

    // 1) QKV projection
    {
        dim3 grid(QKV_N / 128, S / 128);
        gemm_tc_kernel<<<grid, 256, GT_SMEM_BYTES>>>(hidden_t, wqkv_t, b_qkv,
                                                     mixed, S, QKV_N, H);
    }

    // 2) Rotary + tf32 pre-round of q/k/v
    {
        dim3 grid(S, NH);
        rotary_kernel<<<grid, 64>>>(mixed);
    }

    // 3) Causal flash attention (1-D grid, qt-major descending, 2 CTAs/SM)
    attn_tc_kernel<<<NQT * NH, 128, ATTN_SMEM_BYTES>>>(mixed, ctx);

    // 4) Dense projection
    {
        dim3 grid(H / 128, S / 128);
        gemm_tc_kernel<<<grid, 256, GT_SMEM_BYTES>>>(ctx, wdense_t, nullptr,
                                                     out, S, H, H);
    }
}

// round 16
// speedup vs baseline: 1.0148x; 1.0148x over previous
#include <cuda_runtime.h>
#include <cuda_bf16.h>
#include <math.h>
#include <stdint.h>

// Problem constants
#define S 2048
#define H 2048
#define NH 16
#define HD 128
#define QKV_N (3 * H)         // 6144
#define MIXED_W (3 * HD * NH) // 6144
#define HEAD_W (3 * HD)       // 384

// Scratch
__device__ float g_mixed[(size_t)S * QKV_N];
__device__ float g_ctx[(size_t)S * H];
__device__ float g_hidden_t[(size_t)S * H];
__device__ float g_wqkv_t[(size_t)QKV_N * H];
__device__ float g_wdense_t[(size_t)H * H];

// ---------------------------------------------------------------------------
// Helpers
// ---------------------------------------------------------------------------
__device__ __forceinline__ uint32_t smem_to_u32(const void* p) {
    uint32_t a;
    asm("{ .reg .u64 t; cvta.to.shared.u64 t, %1; cvt.u32.u64 %0, t; }" : "=r"(a) : "l"(p));
    return a;
}
__device__ __forceinline__ uint32_t f32_to_tf32(float f) {
    uint32_t r;
    asm("cvt.rna.tf32.f32 %0, %1;" : "=r"(r) : "f"(f));
    return r;
}
__device__ __forceinline__ float tf32_round(float f) {
    return __uint_as_float(f32_to_tf32(f));
}
__device__ __forceinline__ uint32_t pack_f16x2(float lo, float hi) {
    uint32_t d;
    asm("cvt.rn.f16x2.f32 %0, %1, %2;" : "=r"(d) : "f"(hi), "f"(lo));
    return d;
}
__device__ __forceinline__ float fexp2(float x) {
    float y;
    asm("ex2.approx.ftz.f32 %0, %1;" : "=f"(y) : "f"(x));
    return y;
}
#define CP_ASYNC16(dst, src) \
    asm volatile("cp.async.cg.shared.global [%0], [%1], 16;" :: "r"(dst), "l"(src) : "memory")
#define CP_ASYNC_COMMIT() asm volatile("cp.async.commit_group;" ::: "memory")
#define CP_ASYNC_WAIT(n)  asm volatile("cp.async.wait_group %0;" :: "n"(n) : "memory")

__device__ __forceinline__ void mma_tf32(
    float c[4], const uint32_t a[4], const uint32_t b[2])
{
    asm volatile(
        "mma.sync.aligned.m16n8k8.row.col.f32.tf32.tf32.f32 "
        "{%0,%1,%2,%3}, {%4,%5,%6,%7}, {%8,%9}, {%0,%1,%2,%3};"
        : "+f"(c[0]), "+f"(c[1]), "+f"(c[2]), "+f"(c[3])
        : "r"(a[0]), "r"(a[1]), "r"(a[2]), "r"(a[3]), "r"(b[0]), "r"(b[1]));
}
__device__ __forceinline__ void mma_f16(
    float c[4], const uint32_t a[4], uint32_t b0, uint32_t b1)
{
    asm volatile(
        "mma.sync.aligned.m16n8k16.row.col.f32.f16.f16.f32 "
        "{%0,%1,%2,%3}, {%4,%5,%6,%7}, {%8,%9}, {%0,%1,%2,%3};"
        : "+f"(c[0]), "+f"(c[1]), "+f"(c[2]), "+f"(c[3])
        : "r"(a[0]), "r"(a[1]), "r"(a[2]), "r"(a[3]), "r"(b0), "r"(b1));
}
__device__ __forceinline__ uint32_t f4c(const float4& v, int j) {
    const float* p = (const float*)&v;
    return __float_as_uint(p[j]);
}

// ---------------------------------------------------------------------------
// Fused tf32 pre-round of all three GEMM operand tensors (one launch)
// ---------------------------------------------------------------------------
#define N4_HID ((S * H) / 4)
#define N4_WQKV ((QKV_N * H) / 4)
#define N4_WD ((H * H) / 4)
#define N4_TOT (N4_HID + N4_WQKV + N4_WD)

__global__ void round_all_kernel(const float4* __restrict__ hid,
                                 const float4* __restrict__ wq,
                                 const float4* __restrict__ wd,
                                 float4* __restrict__ hid_o,
                                 float4* __restrict__ wq_o,
                                 float4* __restrict__ wd_o)
{
    for (int i = blockIdx.x * blockDim.x + threadIdx.x; i < N4_TOT;
         i += gridDim.x * blockDim.x) {
        const float4* src;
        float4* dst;
        int j = i;
        if (j < N4_HID) { src = hid; dst = hid_o; }
        else if (j < N4_HID + N4_WQKV) { j -= N4_HID; src = wq; dst = wq_o; }
        else { j -= N4_HID + N4_WQKV; src = wd; dst = wd_o; }
        float4 v = src[j];
        v.x = tf32_round(v.x); v.y = tf32_round(v.y);
        v.z = tf32_round(v.z); v.w = tf32_round(v.w);
        dst[j] = v;
    }
}

// ---------------------------------------------------------------------------
// tf32 mma.sync GEMM (unchanged from R15, passing): BM=BN=128, BK=32,
// 256 threads, 3-stage cp.async, one barrier/chunk, WAIT(0) on last iter.
// ---------------------------------------------------------------------------
#define TSTR 36
#define TILE_WORDS (128 * TSTR)                  // 4608
#define GT_SMEM_BYTES (6 * TILE_WORDS * 4)       // 110592

__global__ __launch_bounds__(256) void gemm_tc_kernel(
    const float* __restrict__ A, const float* __restrict__ B,
    const float* __restrict__ bias, float* __restrict__ C,
    int M, int N, int K)
{
    extern __shared__ float smf[];
    const uint32_t smem_base = smem_to_u32(smf);
    const int tid  = threadIdx.x;
    const int wid  = tid >> 5;
    const int lane = tid & 31;
    const int wm = wid >> 2;
    const int wn = wid & 3;
    const int bm = blockIdx.y * 128;
    const int bn = blockIdx.x * 128;

    const int lr = lane >> 2;
    const int lc = lane & 3;

    const int ld_row = tid >> 3;
    const int ld_k4  = (tid & 7) << 2;

    float c[4][4][4];
#pragma unroll
    for (int mt = 0; mt < 4; mt++)
#pragma unroll
        for (int nt = 0; nt < 4; nt++)
#pragma unroll
            for (int r = 0; r < 4; r++) c[mt][nt][r] = 0.f;

    const int NK = K >> 5;

    auto load_tiles = [&](int i) {
        const int st = i % 3;
        const int k0 = i << 5;
        const uint32_t abase = smem_base + (uint32_t)(st * 2 * TILE_WORDS) * 4;
        const uint32_t bbase = abase + TILE_WORDS * 4;
#pragma unroll
        for (int j = 0; j < 4; j++) {
            const int m = ld_row + 32 * j;
            const uint32_t soff = (uint32_t)(m * TSTR + ld_k4) * 4;
            CP_ASYNC16(abase + soff, A + (size_t)(bm + m) * K + k0 + ld_k4);
            CP_ASYNC16(bbase + soff, B + (size_t)(bn + m) * K + k0 + ld_k4);
        }
        CP_ASYNC_COMMIT();
    };

    load_tiles(0);
    load_tiles(1);

    for (int i = 0; i < NK; i++) {
        if (i + 1 < NK) { CP_ASYNC_WAIT(1); }
        else            { CP_ASYNC_WAIT(0); }
        __syncthreads();

        if (i + 2 < NK) load_tiles(i + 2);

        const float* As = smf + (size_t)(i % 3) * 2 * TILE_WORDS;
        const float* Bs = As + TILE_WORDS;

#pragma unroll
        for (int ks = 0; ks < 4; ks++) {
            const int kc = ks * 8 + lc;
            uint32_t af[4][4];
#pragma unroll
            for (int mt = 0; mt < 4; mt++) {
                const int row = wm * 64 + mt * 16 + lr;
                af[mt][0] = __float_as_uint(As[row * TSTR + kc]);
                af[mt][1] = __float_as_uint(As[(row + 8) * TSTR + kc]);
                af[mt][2] = __float_as_uint(As[row * TSTR + kc + 4]);
                af[mt][3] = __float_as_uint(As[(row + 8) * TSTR + kc + 4]);
            }
            uint32_t bf[4][2];
#pragma unroll
            for (int nt = 0; nt < 4; nt++) {
                const int ncol = wn * 32 + nt * 8 + lr;
                bf[nt][0] = __float_as_uint(Bs[ncol * TSTR + kc]);
                bf[nt][1] = __float_as_uint(Bs[ncol * TSTR + kc + 4]);
            }
#pragma unroll
            for (int mt = 0; mt < 4; mt++)
#pragma unroll
                for (int nt = 0; nt < 4; nt++)
                    mma_tf32(c[mt][nt], af[mt], bf[nt]);
        }
    }

#pragma unroll
    for (int nt = 0; nt < 4; nt++) {
        const int col = bn + wn * 32 + nt * 8 + lc * 2;
        float b0 = 0.f, b1 = 0.f;
        if (bias) { b0 = bias[col]; b1 = bias[col + 1]; }
#pragma unroll
        for (int mt = 0; mt < 4; mt++) {
            const int row = bm + wm * 64 + mt * 16 + lr;
            float2 v0 = make_float2(c[mt][nt][0] + b0, c[mt][nt][1] + b1);
            float2 v1 = make_float2(c[mt][nt][2] + b0, c[mt][nt][3] + b1);
            *(float2*)(C + (size_t)row * N + col) = v0;
            *(float2*)(C + (size_t)(row + 8) * N + col) = v1;
        }
    }
}

// ---------------------------------------------------------------------------
// Rotary embedding + tf32 pre-round. Q pre-scaled by (1/sqrt(128))*log2(e)
// so attention softmax can use raw ex2.
// ---------------------------------------------------------------------------
__global__ void rotary_kernel(float* __restrict__ mixed)
{
    const int s = blockIdx.x;
    const int n = blockIdx.y;
    const int d = threadIdx.x;  // 0..63
    const float inv_freq = expf(-(float)d * (9.210340371976184f / 64.0f));
    const float freq = (float)s * inv_freq;
    float si, c;
    sincosf(freq, &si, &c);
    const float qscale = 0.1275174512f;   // (1/sqrt(128)) * log2(e)

    float* base = mixed + (size_t)s * MIXED_W + n * HEAD_W;
    {
        float* p = base;
        const float x1 = p[d];
        const float x2 = p[d + 64];
        p[d]      = tf32_round(qscale * (x1 * c - x2 * si));
        p[d + 64] = tf32_round(qscale * (x2 * c + x1 * si));
    }
    {
        float* p = base + HD;
        const float x1 = p[d];
        const float x2 = p[d + 64];
        p[d]      = tf32_round(x1 * c - x2 * si);
        p[d + 64] = tf32_round(x2 * c + x1 * si);
    }
    {
        float* p = base + 2 * HD;
        p[d]      = tf32_round(p[d]);
        p[d + 64] = tf32_round(p[d + 64]);
    }
}

// ---------------------------------------------------------------------------
// Flash attention (causal): tf32 QK^T + fp16-P PV (FA2 fragment-reuse trick).
// AQ=64, AK=64, single KV buffer, 128 threads (4 warps x 16 q-rows),
// 2 CTAs/SM. Softmax in log2 domain (Q pre-scaled by log2e).
// C-frag of S (row lr, cols 2lc,2lc+1) == fp16 A-frag layout -> no shuffles.
// VST=140: V B-frag scalar LDS conflict-free (row offsets mod 32 distinct).
// ---------------------------------------------------------------------------
#define AQ 64
#define AK 64
#define QST 144
#define QST4 (QST / 4)
#define VST 140
#define QWRD (AQ * QST)             // 9216
#define KWRD (AK * QST)             // 9216
#define VWRD (AK * VST)             // 8960
#define ATTN_SMEM_BYTES ((QWRD + KWRD + VWRD) * 4)  // 109568 B
#define NQT (S / AQ)   // 32

__global__ __launch_bounds__(128, 2) void attn_tc_kernel(
    const float* __restrict__ mixed, float* __restrict__ ctx)
{
    extern __shared__ float sf[];
    const uint32_t smem_base = smem_to_u32(sf);

    const int tid  = threadIdx.x;
    const int wid  = tid >> 5;       // 0..3
    const int lane = tid & 31;
    const int lr = lane >> 2;
    const int lc = lane & 3;
    const int bid = blockIdx.x;
    const int h  = bid & (NH - 1);
    const int qt = NQT - 1 - (bid >> 4);   // qt-major, biggest first
    const int r0 = qt * AQ;
    const int m0 = wid * 16;
    const size_t hoff = (size_t)h * HEAD_W;

    auto load_kv = [&](int kt) {
        const uint32_t kb = smem_base + (uint32_t)QWRD * 4;
        const uint32_t vb = kb + KWRD * 4;
        const float* kg = mixed + (size_t)(kt * AK) * MIXED_W + hoff + HD;
        const float* vg = kg + HD;
#pragma unroll
        for (int it = 0; it < 16; it++) {
            const int u = tid + (it << 7);           // 0..2047
            const int row = u >> 5, c4 = (u & 31) << 2;
            CP_ASYNC16(kb + (uint32_t)(row * QST + c4) * 4, kg + (size_t)row * MIXED_W + c4);
            CP_ASYNC16(vb + (uint32_t)(row * VST + c4) * 4, vg + (size_t)row * MIXED_W + c4);
        }
        CP_ASYNC_COMMIT();
    };

    // stage Q (pre-scaled by qscale*log2e, tf32-rounded) and first KV tile
    {
        const float* qg = mixed + (size_t)r0 * MIXED_W + hoff;
#pragma unroll
        for (int it = 0; it < 16; it++) {
            const int u = tid + (it << 7);
            const int row = u >> 5, c4 = (u & 31) << 2;
            CP_ASYNC16(smem_base + (uint32_t)(row * QST + c4) * 4,
                       qg + (size_t)row * MIXED_W + c4);
        }
        CP_ASYNC_COMMIT();
    }
    load_kv(0);

    const int nkt = qt + 1;

    float co[16][4];
#pragma unroll
    for (int nt = 0; nt < 16; nt++)
#pragma unroll
        for (int r = 0; r < 4; r++) co[nt][r] = 0.f;
    float mrow[2] = {-1e30f, -1e30f};
    float lrow[2] = {0.f, 0.f};

    const float* Ks = sf + QWRD;
    const float* Vs = Ks + KWRD;
    const float4* Qs4 = (const float4*)sf;
    const float4* Ks4 = (const float4*)Ks;

    for (int kt = 0; kt < nkt; kt++) {
        CP_ASYNC_WAIT(0);
        __syncthreads();   // KV(kt) (and Q on first iter) visible to all

        const int c0 = kt * AK;

        // ---- S = Q K^T (tf32, permuted-k LDS.128 fragments) ----
        float s[8][4];
#pragma unroll
        for (int nt = 0; nt < 8; nt++)
#pragma unroll
            for (int r = 0; r < 4; r++) s[nt][r] = 0.f;

#pragma unroll
        for (int ch = 0; ch < 4; ch++) {
            const int cb = ch * 8;
            const int row = m0 + lr;
            float4 qa[2][2];
            qa[0][0] = Qs4[row * QST4 + cb + lc];
            qa[0][1] = Qs4[row * QST4 + cb + 4 + lc];
            qa[1][0] = Qs4[(row + 8) * QST4 + cb + lc];
            qa[1][1] = Qs4[(row + 8) * QST4 + cb + 4 + lc];
#pragma unroll
            for (int g = 0; g < 2; g++) {
                float4 kb4[4][2];
#pragma unroll
                for (int q = 0; q < 4; q++) {
                    const int col = (g * 4 + q) * 8 + lr;
                    kb4[q][0] = Ks4[col * QST4 + cb + lc];
                    kb4[q][1] = Ks4[col * QST4 + cb + 4 + lc];
                }
#pragma unroll
                for (int j = 0; j < 4; j++) {
                    uint32_t a[4] = { f4c(qa[0][0], j), f4c(qa[1][0], j),
                                      f4c(qa[0][1], j), f4c(qa[1][1], j) };
#pragma unroll
                    for (int q = 0; q < 4; q++) {
                        uint32_t b[2] = { f4c(kb4[q][0], j), f4c(kb4[q][1], j) };
                        mma_tf32(s[g * 4 + q], a, b);
                    }
                }
            }
        }

        // ---- causal mask (diagonal tile only) ----
        if (c0 + AK - 1 > r0 + m0) {
            const int rga = r0 + m0 + lr;
            const int rgb = rga + 8;
#pragma unroll
            for (int nt = 0; nt < 8; nt++) {
                const int cg0 = c0 + nt * 8 + lc * 2;
                const int cg1 = cg0 + 1;
                if (cg0 > rga) s[nt][0] = -1e30f;
                if (cg1 > rga) s[nt][1] = -1e30f;
                if (cg0 > rgb) s[nt][2] = -1e30f;
                if (cg1 > rgb) s[nt][3] = -1e30f;
            }
        }

        // ---- online softmax (log2 domain: p = 2^(s - m)) ----
#pragma unroll
        for (int hh = 0; hh < 2; hh++) {
            float mx = -1e30f;
#pragma unroll
            for (int nt = 0; nt < 8; nt++)
                mx = fmaxf(mx, fmaxf(s[nt][2 * hh], s[nt][2 * hh + 1]));
            mx = fmaxf(mx, __shfl_xor_sync(0xffffffffu, mx, 1));
            mx = fmaxf(mx, __shfl_xor_sync(0xffffffffu, mx, 2));
            const float m_new = fmaxf(mrow[hh], mx);
            const float sc = fexp2(mrow[hh] - m_new);
            float rs = 0.f;
#pragma unroll
            for (int nt = 0; nt < 8; nt++) {
                const float p0 = fexp2(s[nt][2 * hh] - m_new);
                const float p1 = fexp2(s[nt][2 * hh + 1] - m_new);
                s[nt][2 * hh] = p0;
                s[nt][2 * hh + 1] = p1;
                rs += p0 + p1;
            }
            rs += __shfl_xor_sync(0xffffffffu, rs, 1);
            rs += __shfl_xor_sync(0xffffffffu, rs, 2);
            lrow[hh] = lrow[hh] * sc + rs;
            mrow[hh] = m_new;
#pragma unroll
            for (int nt = 0; nt < 16; nt++) {
                co[nt][2 * hh]     *= sc;
                co[nt][2 * hh + 1] *= sc;
            }
        }

        // ---- O += P V (fp16 P via C->A fragment reuse, m16n8k16) ----
#pragma unroll
        for (int t = 0; t < 4; t++) {
            uint32_t pa[4];
            pa[0] = pack_f16x2(s[2 * t][0],     s[2 * t][1]);
            pa[1] = pack_f16x2(s[2 * t][2],     s[2 * t][3]);
            pa[2] = pack_f16x2(s[2 * t + 1][0], s[2 * t + 1][1]);
            pa[3] = pack_f16x2(s[2 * t + 1][2], s[2 * t + 1][3]);
            const int kb = t * 16;
            const float* v0 = Vs + (kb + 2 * lc) * VST;
            const float* v1 = v0 + VST;
            const float* v8 = Vs + (kb + 2 * lc + 8) * VST;
            const float* v9 = v8 + VST;
#pragma unroll
            for (int nt = 0; nt < 16; nt++) {
                const int d = nt * 8 + lr;
                const uint32_t vb0 = pack_f16x2(v0[d], v1[d]);
                const uint32_t vb1 = pack_f16x2(v8[d], v9[d]);
                mma_f16(co[nt], pa, vb0, vb1);
            }
        }

        __syncthreads();   // all warps done reading KV(kt)
        if (kt + 1 < nkt) load_kv(kt + 1);
    }

    // ---- normalize + store (tf32-rounded for dense GEMM) ----
    {
        const float li0 = 1.f / lrow[0];
        const float li1 = 1.f / lrow[1];
        const int row = r0 + m0 + lr;
#pragma unroll
        for (int nt = 0; nt < 16; nt++) {
            const int col = h * HD + nt * 8 + lc * 2;
            *(float2*)(ctx + (size_t)row * H + col) =
                make_float2(tf32_round(co[nt][0] * li0), tf32_round(co[nt][1] * li0));
            *(float2*)(ctx + (size_t)(row + 8) * H + col) =
                make_float2(tf32_round(co[nt][2] * li1), tf32_round(co[nt][3] * li1));
        }
    }
}

// ---------------------------------------------------------------------------
// Launch
// ---------------------------------------------------------------------------
extern "C" void kernel_launch(void* const* d_in, const int* in_sizes, int n_in,
                              void* d_out, int out_size)
{
    const float* hidden  = (const float*)d_in[0];
    const float* w_qkv   = (const float*)d_in[2];
    const float* b_qkv   = (const float*)d_in[3];
    const float* w_dense = (const float*)d_in[4];
    float* out = (float*)d_out;

    float *mixed, *ctx, *hidden_t, *wqkv_t, *wdense_t;
    cudaGetSymbolAddress((void**)&mixed, g_mixed);
    cudaGetSymbolAddress((void**)&ctx, g_ctx);
    cudaGetSymbolAddress((void**)&hidden_t, g_hidden_t);
    cudaGetSymbolAddress((void**)&wqkv_t, g_wqkv_t);
    cudaGetSymbolAddress((void**)&wdense_t, g_wdense_t);

    cudaFuncSetAttribute(gemm_tc_kernel,
                         cudaFuncAttributeMaxDynamicSharedMemorySize, GT_SMEM_BYTES);
    cudaFuncSetAttribute(attn_tc_kernel,
                         cudaFuncAttributeMaxDynamicSharedMemorySize, ATTN_SMEM_BYTES);

    // 0) fused tf32 pre-round of all GEMM operands (one launch)
    round_all_kernel<<<2048, 256>>>((const float4*)hidden, (const float4*)w_qkv,
                                    (const float4*)w_dense, (float4*)hidden_t,
                                    (float4*)wqkv_t, (float4*)wdense_t);

    // 1) QKV projection
    {
        dim3 grid(QKV_N / 128, S / 128);
        gemm_tc_kernel<<<grid, 256, GT_SMEM_BYTES>>>(hidden_t, wqkv_t, b_qkv,
                                                     mixed, S, QKV_N, H);
    }

    // 2) Rotary + tf32 pre-round of q/k/v (q pre-scaled into log2 domain)
    {
        dim3 grid(S, NH);
        rotary_kernel<<<grid, 64>>>(mixed);
    }

    // 3) Causal flash attention (1-D grid, qt-major descending, 2 CTAs/SM)
    attn_tc_kernel<<<NQT * NH, 128, ATTN_SMEM_BYTES>>>(mixed, ctx);

    // 4) Dense projection
    {
        dim3 grid(H / 128, S / 128);
        gemm_tc_kernel<<<grid, 256, GT_SMEM_BYTES>>>(ctx, wdense_t, nullptr,
                                                     out, S, H, H);
    }
}

// round 17
// speedup vs baseline: 1.3370x; 1.3176x over previous
#include <cuda_runtime.h>
#include <cuda_fp16.h>
#include <cuda_bf16.h>
#include <math.h>
#include <stdint.h>

// Problem constants
#define S 2048
#define H 2048
#define NH 16
#define HD 128
#define QKV_N (3 * H)         // 6144
#define MIXED_W (3 * HD * NH) // 6144
#define HEAD_W (3 * HD)       // 384

// Scratch
__device__ float  g_mixed[(size_t)S * QKV_N];
__device__ __half g_ctx_h[(size_t)S * H];
__device__ __half g_hidden_h[(size_t)S * H];
__device__ __half g_wqkv_h[(size_t)QKV_N * H];
__device__ __half g_wdense_h[(size_t)H * H];

// ---------------------------------------------------------------------------
// Helpers
// ---------------------------------------------------------------------------
__device__ __forceinline__ uint32_t smem_to_u32(const void* p) {
    uint32_t a;
    asm("{ .reg .u64 t; cvta.to.shared.u64 t, %1; cvt.u32.u64 %0, t; }" : "=r"(a) : "l"(p));
    return a;
}
__device__ __forceinline__ uint32_t f32_to_tf32(float f) {
    uint32_t r;
    asm("cvt.rna.tf32.f32 %0, %1;" : "=r"(r) : "f"(f));
    return r;
}
__device__ __forceinline__ float tf32_round(float f) {
    return __uint_as_float(f32_to_tf32(f));
}
__device__ __forceinline__ uint32_t pack_f16x2(float lo, float hi) {
    uint32_t d;
    asm("cvt.rn.f16x2.f32 %0, %1, %2;" : "=r"(d) : "f"(hi), "f"(lo));
    return d;
}
__device__ __forceinline__ float fexp2(float x) {
    float y;
    asm("ex2.approx.ftz.f32 %0, %1;" : "=f"(y) : "f"(x));
    return y;
}
#define CP_ASYNC16(dst, src) \
    asm volatile("cp.async.cg.shared.global [%0], [%1], 16;" :: "r"(dst), "l"(src) : "memory")
#define CP_ASYNC_COMMIT() asm volatile("cp.async.commit_group;" ::: "memory")
#define CP_ASYNC_WAIT(n)  asm volatile("cp.async.wait_group %0;" :: "n"(n) : "memory")

__device__ __forceinline__ void mma_tf32(
    float c[4], const uint32_t a[4], const uint32_t b[2])
{
    asm volatile(
        "mma.sync.aligned.m16n8k8.row.col.f32.tf32.tf32.f32 "
        "{%0,%1,%2,%3}, {%4,%5,%6,%7}, {%8,%9}, {%0,%1,%2,%3};"
        : "+f"(c[0]), "+f"(c[1]), "+f"(c[2]), "+f"(c[3])
        : "r"(a[0]), "r"(a[1]), "r"(a[2]), "r"(a[3]), "r"(b[0]), "r"(b[1]));
}
__device__ __forceinline__ void mma_f16(
    float c[4], const uint32_t a[4], uint32_t b0, uint32_t b1)
{
    asm volatile(
        "mma.sync.aligned.m16n8k16.row.col.f32.f16.f16.f32 "
        "{%0,%1,%2,%3}, {%4,%5,%6,%7}, {%8,%9}, {%0,%1,%2,%3};"
        : "+f"(c[0]), "+f"(c[1]), "+f"(c[2]), "+f"(c[3])
        : "r"(a[0]), "r"(a[1]), "r"(a[2]), "r"(a[3]), "r"(b0), "r"(b1));
}
__device__ __forceinline__ uint32_t f4c(const float4& v, int j) {
    const float* p = (const float*)&v;
    return __float_as_uint(p[j]);
}

// ---------------------------------------------------------------------------
// Fused fp16 conversion of all three GEMM operand tensors (one launch)
// ---------------------------------------------------------------------------
#define N4_HID ((S * H) / 4)
#define N4_WQKV ((QKV_N * H) / 4)
#define N4_WD ((H * H) / 4)
#define N4_TOT (N4_HID + N4_WQKV + N4_WD)

__global__ void round_all_kernel(const float4* __restrict__ hid,
                                 const float4* __restrict__ wq,
                                 const float4* __restrict__ wd,
                                 uint2* __restrict__ hid_o,
                                 uint2* __restrict__ wq_o,
                                 uint2* __restrict__ wd_o)
{
    for (int i = blockIdx.x * blockDim.x + threadIdx.x; i < N4_TOT;
         i += gridDim.x * blockDim.x) {
        const float4* src;
        uint2* dst;
        int j = i;
        if (j < N4_HID) { src = hid; dst = hid_o; }
        else if (j < N4_HID + N4_WQKV) { j -= N4_HID; src = wq; dst = wq_o; }
        else { j -= N4_HID + N4_WQKV; src = wd; dst = wd_o; }
        float4 v = src[j];
        dst[j] = make_uint2(pack_f16x2(v.x, v.y), pack_f16x2(v.z, v.w));
    }
}

// ---------------------------------------------------------------------------
// fp16 mma.sync GEMM: C[M,N](f32) = A[M,K](f16)*B[N,K](f16)^T (+bias f32)
// BM=BN=128, BK=32, 256 threads (8 warps, 2x4 of 64x32 warp tiles),
// m16n8k16, f32 accum. 3-stage cp.async, one barrier/chunk, WAIT(0) on last.
// smem rows: 32 halves + 8 pad -> word-stride 20 (==4 mod 8): conflict-free.
// ---------------------------------------------------------------------------
#define HSTR 20                                   // 32-bit words per smem row
#define HTILE_WORDS (128 * HSTR)                  // 2560 words / operand tile
#define GT_SMEM_BYTES (6 * HTILE_WORDS * 4)       // 61440

__global__ __launch_bounds__(256) void gemm_tc_kernel(
    const __half* __restrict__ A, const __half* __restrict__ B,
    const float* __restrict__ bias, float* __restrict__ C,
    int M, int N, int K)
{
    extern __shared__ uint32_t smw[];
    const uint32_t smem_base = smem_to_u32(smw);
    const int tid  = threadIdx.x;
    const int wid  = tid >> 5;
    const int lane = tid & 31;
    const int wm = wid >> 2;         // 0..1
    const int wn = wid & 3;          // 0..3
    const int bm = blockIdx.y * 128;
    const int bn = blockIdx.x * 128;

    const int lr = lane >> 2;
    const int lc = lane & 3;

    const int ld_row = tid >> 2;         // 0..63 (+64 per j)
    const int ld_seg = tid & 3;          // 16B segment within 64B row

    float c[4][4][4];
#pragma unroll
    for (int mt = 0; mt < 4; mt++)
#pragma unroll
        for (int nt = 0; nt < 4; nt++)
#pragma unroll
            for (int r = 0; r < 4; r++) c[mt][nt][r] = 0.f;

    const int NK = K >> 5;   // chunks of 32 halves

    auto load_tiles = [&](int i) {
        const int st = i % 3;
        const int k0 = i << 5;
        const uint32_t abase = smem_base + (uint32_t)(st * 2 * HTILE_WORDS) * 4;
        const uint32_t bbase = abase + HTILE_WORDS * 4;
#pragma unroll
        for (int j = 0; j < 2; j++) {
            const int row = ld_row + 64 * j;
            const uint32_t soff = (uint32_t)(row * HSTR + ld_seg * 4) * 4;
            const int goff = k0 + ld_seg * 8;
            CP_ASYNC16(abase + soff, A + (size_t)(bm + row) * K + goff);
            CP_ASYNC16(bbase + soff, B + (size_t)(bn + row) * K + goff);
        }
        CP_ASYNC_COMMIT();
    };

    load_tiles(0);
    load_tiles(1);

    for (int i = 0; i < NK; i++) {
        if (i + 1 < NK) { CP_ASYNC_WAIT(1); }   // newest group may stay pending
        else            { CP_ASYNC_WAIT(0); }   // last iter: drain fully
        __syncthreads();

        if (i + 2 < NK) load_tiles(i + 2);

        const uint32_t* As = smw + (size_t)(i % 3) * 2 * HTILE_WORDS;
        const uint32_t* Bs = As + HTILE_WORDS;

#pragma unroll
        for (int ks = 0; ks < 2; ks++) {        // two k16 slices
            const int wb = ks * 8 + lc;
            uint32_t af[4][4];
#pragma unroll
            for (int mt = 0; mt < 4; mt++) {
                const int row = wm * 64 + mt * 16 + lr;
                af[mt][0] = As[row * HSTR + wb];
                af[mt][1] = As[(row + 8) * HSTR + wb];
                af[mt][2] = As[row * HSTR + wb + 4];
                af[mt][3] = As[(row + 8) * HSTR + wb + 4];
            }
            uint32_t bf[4][2];
#pragma unroll
            for (int nt = 0; nt < 4; nt++) {
                const int ncol = wn * 32 + nt * 8 + lr;
                bf[nt][0] = Bs[ncol * HSTR + wb];
                bf[nt][1] = Bs[ncol * HSTR + wb + 4];
            }
#pragma unroll
            for (int mt = 0; mt < 4; mt++)
#pragma unroll
                for (int nt = 0; nt < 4; nt++)
                    mma_f16(c[mt][nt], af[mt], bf[nt][0], bf[nt][1]);
        }
    }

#pragma unroll
    for (int nt = 0; nt < 4; nt++) {
        const int col = bn + wn * 32 + nt * 8 + lc * 2;
        float b0 = 0.f, b1 = 0.f;
        if (bias) { b0 = bias[col]; b1 = bias[col + 1]; }
#pragma unroll
        for (int mt = 0; mt < 4; mt++) {
            const int row = bm + wm * 64 + mt * 16 + lr;
            float2 v0 = make_float2(c[mt][nt][0] + b0, c[mt][nt][1] + b1);
            float2 v1 = make_float2(c[mt][nt][2] + b0, c[mt][nt][3] + b1);
            *(float2*)(C + (size_t)row * N + col) = v0;
            *(float2*)(C + (size_t)(row + 8) * N + col) = v1;
        }
    }
}

// ---------------------------------------------------------------------------
// Rotary embedding + tf32 pre-round. Q pre-scaled by (1/sqrt(128))*log2(e).
// ---------------------------------------------------------------------------
__global__ void rotary_kernel(float* __restrict__ mixed)
{
    const int s = blockIdx.x;
    const int n = blockIdx.y;
    const int d = threadIdx.x;  // 0..63
    const float inv_freq = expf(-(float)d * (9.210340371976184f / 64.0f));
    const float freq = (float)s * inv_freq;
    float si, c;
    sincosf(freq, &si, &c);
    const float qscale = 0.1275174512f;   // (1/sqrt(128)) * log2(e)

    float* base = mixed + (size_t)s * MIXED_W + n * HEAD_W;
    {
        float* p = base;
        const float x1 = p[d];
        const float x2 = p[d + 64];
        p[d]      = tf32_round(qscale * (x1 * c - x2 * si));
        p[d + 64] = tf32_round(qscale * (x2 * c + x1 * si));
    }
    {
        float* p = base + HD;
        const float x1 = p[d];
        const float x2 = p[d + 64];
        p[d]      = tf32_round(x1 * c - x2 * si);
        p[d + 64] = tf32_round(x2 * c + x1 * si);
    }
    {
        float* p = base + 2 * HD;
        p[d]      = tf32_round(p[d]);
        p[d + 64] = tf32_round(p[d + 64]);
    }
}

// ---------------------------------------------------------------------------
// Flash attention (causal): tf32 QK^T + fp16-P PV. Unchanged R16 internals;
// ctx now written as fp16 for the fp16 dense GEMM.
// ---------------------------------------------------------------------------
#define AQ 64
#define AK 64
#define QST 144
#define QST4 (QST / 4)
#define VST 140
#define QWRD (AQ * QST)             // 9216
#define KWRD (AK * QST)             // 9216
#define VWRD (AK * VST)             // 8960
#define ATTN_SMEM_BYTES ((QWRD + KWRD + VWRD) * 4)  // 109568 B
#define NQT (S / AQ)   // 32

__global__ __launch_bounds__(128, 2) void attn_tc_kernel(
    const float* __restrict__ mixed, __half* __restrict__ ctxh)
{
    extern __shared__ float sf[];
    const uint32_t smem_base = smem_to_u32(sf);

    const int tid  = threadIdx.x;
    const int wid  = tid >> 5;       // 0..3
    const int lane = tid & 31;
    const int lr = lane >> 2;
    const int lc = lane & 3;
    const int bid = blockIdx.x;
    const int h  = bid & (NH - 1);
    const int qt = NQT - 1 - (bid >> 4);   // qt-major, biggest first
    const int r0 = qt * AQ;
    const int m0 = wid * 16;
    const size_t hoff = (size_t)h * HEAD_W;

    auto load_kv = [&](int kt) {
        const uint32_t kb = smem_base + (uint32_t)QWRD * 4;
        const uint32_t vb = kb + KWRD * 4;
        const float* kg = mixed + (size_t)(kt * AK) * MIXED_W + hoff + HD;
        const float* vg = kg + HD;
#pragma unroll
        for (int it = 0; it < 16; it++) {
            const int u = tid + (it << 7);           // 0..2047
            const int row = u >> 5, c4 = (u & 31) << 2;
            CP_ASYNC16(kb + (uint32_t)(row * QST + c4) * 4, kg + (size_t)row * MIXED_W + c4);
            CP_ASYNC16(vb + (uint32_t)(row * VST + c4) * 4, vg + (size_t)row * MIXED_W + c4);
        }
        CP_ASYNC_COMMIT();
    };

    // stage Q and first KV tile
    {
        const float* qg = mixed + (size_t)r0 * MIXED_W + hoff;
#pragma unroll
        for (int it = 0; it < 16; it++) {
            const int u = tid + (it << 7);
            const int row = u >> 5, c4 = (u & 31) << 2;
            CP_ASYNC16(smem_base + (uint32_t)(row * QST + c4) * 4,
                       qg + (size_t)row * MIXED_W + c4);
        }
        CP_ASYNC_COMMIT();
    }
    load_kv(0);

    const int nkt = qt + 1;

    float co[16][4];
#pragma unroll
    for (int nt = 0; nt < 16; nt++)
#pragma unroll
        for (int r = 0; r < 4; r++) co[nt][r] = 0.f;
    float mrow[2] = {-1e30f, -1e30f};
    float lrow[2] = {0.f, 0.f};

    const float* Ks = sf + QWRD;
    const float* Vs = Ks + KWRD;
    const float4* Qs4 = (const float4*)sf;
    const float4* Ks4 = (const float4*)Ks;

    for (int kt = 0; kt < nkt; kt++) {
        CP_ASYNC_WAIT(0);
        __syncthreads();   // KV(kt) (and Q on first iter) visible to all

        const int c0 = kt * AK;

        // ---- S = Q K^T (tf32, permuted-k LDS.128 fragments) ----
        float s[8][4];
#pragma unroll
        for (int nt = 0; nt < 8; nt++)
#pragma unroll
            for (int r = 0; r < 4; r++) s[nt][r] = 0.f;

#pragma unroll
        for (int ch = 0; ch < 4; ch++) {
            const int cb = ch * 8;
            const int row = m0 + lr;
            float4 qa[2][2];
            qa[0][0] = Qs4[row * QST4 + cb + lc];
            qa[0][1] = Qs4[row * QST4 + cb + 4 + lc];
            qa[1][0] = Qs4[(row + 8) * QST4 + cb + lc];
            qa[1][1] = Qs4[(row + 8) * QST4 + cb + 4 + lc];
#pragma unroll
            for (int g = 0; g < 2; g++) {
                float4 kb4[4][2];
#pragma unroll
                for (int q = 0; q < 4; q++) {
                    const int col = (g * 4 + q) * 8 + lr;
                    kb4[q][0] = Ks4[col * QST4 + cb + lc];
                    kb4[q][1] = Ks4[col * QST4 + cb + 4 + lc];
                }
#pragma unroll
                for (int j = 0; j < 4; j++) {
                    uint32_t a[4] = { f4c(qa[0][0], j), f4c(qa[1][0], j),
                                      f4c(qa[0][1], j), f4c(qa[1][1], j) };
#pragma unroll
                    for (int q = 0; q < 4; q++) {
                        uint32_t b[2] = { f4c(kb4[q][0], j), f4c(kb4[q][1], j) };
                        mma_tf32(s[g * 4 + q], a, b);
                    }
                }
            }
        }

        // ---- causal mask (diagonal tile only) ----
        if (c0 + AK - 1 > r0 + m0) {
            const int rga = r0 + m0 + lr;
            const int rgb = rga + 8;
#pragma unroll
            for (int nt = 0; nt < 8; nt++) {
                const int cg0 = c0 + nt * 8 + lc * 2;
                const int cg1 = cg0 + 1;
                if (cg0 > rga) s[nt][0] = -1e30f;
                if (cg1 > rga) s[nt][1] = -1e30f;
                if (cg0 > rgb) s[nt][2] = -1e30f;
                if (cg1 > rgb) s[nt][3] = -1e30f;
            }
        }

        // ---- online softmax (log2 domain) ----
#pragma unroll
        for (int hh = 0; hh < 2; hh++) {
            float mx = -1e30f;
#pragma unroll
            for (int nt = 0; nt < 8; nt++)
                mx = fmaxf(mx, fmaxf(s[nt][2 * hh], s[nt][2 * hh + 1]));
            mx = fmaxf(mx, __shfl_xor_sync(0xffffffffu, mx, 1));
            mx = fmaxf(mx, __shfl_xor_sync(0xffffffffu, mx, 2));
            const float m_new = fmaxf(mrow[hh], mx);
            const float sc = fexp2(mrow[hh] - m_new);
            float rs = 0.f;
#pragma unroll
            for (int nt = 0; nt < 8; nt++) {
                const float p0 = fexp2(s[nt][2 * hh] - m_new);
                const float p1 = fexp2(s[nt][2 * hh + 1] - m_new);
                s[nt][2 * hh] = p0;
                s[nt][2 * hh + 1] = p1;
                rs += p0 + p1;
            }
            rs += __shfl_xor_sync(0xffffffffu, rs, 1);
            rs += __shfl_xor_sync(0xffffffffu, rs, 2);
            lrow[hh] = lrow[hh] * sc + rs;
            mrow[hh] = m_new;
#pragma unroll
            for (int nt = 0; nt < 16; nt++) {
                co[nt][2 * hh]     *= sc;
                co[nt][2 * hh + 1] *= sc;
            }
        }

        // ---- O += P V (fp16 P via C->A fragment reuse, m16n8k16) ----
#pragma unroll
        for (int t = 0; t < 4; t++) {
            uint32_t pa[4];
            pa[0] = pack_f16x2(s[2 * t][0],     s[2 * t][1]);
            pa[1] = pack_f16x2(s[2 * t][2],     s[2 * t][3]);
            pa[2] = pack_f16x2(s[2 * t + 1][0], s[2 * t + 1][1]);
            pa[3] = pack_f16x2(s[2 * t + 1][2], s[2 * t + 1][3]);
            const int kb = t * 16;
            const float* v0 = Vs + (kb + 2 * lc) * VST;
            const float* v1 = v0 + VST;
            const float* v8 = Vs + (kb + 2 * lc + 8) * VST;
            const float* v9 = v8 + VST;
#pragma unroll
            for (int nt = 0; nt < 16; nt++) {
                const int d = nt * 8 + lr;
                const uint32_t vb0 = pack_f16x2(v0[d], v1[d]);
                const uint32_t vb1 = pack_f16x2(v8[d], v9[d]);
                mma_f16(co[nt], pa, vb0, vb1);
            }
        }

        __syncthreads();   // all warps done reading KV(kt)
        if (kt + 1 < nkt) load_kv(kt + 1);
    }

    // ---- normalize + store ctx as fp16 (for fp16 dense GEMM) ----
    {
        const float li0 = 1.f / lrow[0];
        const float li1 = 1.f / lrow[1];
        const int row = r0 + m0 + lr;
#pragma unroll
        for (int nt = 0; nt < 16; nt++) {
            const int col = h * HD + nt * 8 + lc * 2;
            *(uint32_t*)(ctxh + (size_t)row * H + col) =
                pack_f16x2(co[nt][0] * li0, co[nt][1] * li0);
            *(uint32_t*)(ctxh + (size_t)(row + 8) * H + col) =
                pack_f16x2(co[nt][2] * li1, co[nt][3] * li1);
        }
    }
}

// ---------------------------------------------------------------------------
// Launch
// ---------------------------------------------------------------------------
extern "C" void kernel_launch(void* const* d_in, const int* in_sizes, int n_in,
                              void* d_out, int out_size)
{
    const float* hidden  = (const float*)d_in[0];
    const float* w_qkv   = (const float*)d_in[2];
    const float* b_qkv   = (const float*)d_in[3];
    const float* w_dense = (const float*)d_in[4];
    float* out = (float*)d_out;

    float* mixed;
    __half *ctxh, *hidden_h, *wqkv_h, *wdense_h;
    cudaGetSymbolAddress((void**)&mixed, g_mixed);
    cudaGetSymbolAddress((void**)&ctxh, g_ctx_h);
    cudaGetSymbolAddress((void**)&hidden_h, g_hidden_h);
    cudaGetSymbolAddress((void**)&wqkv_h, g_wqkv_h);
    cudaGetSymbolAddress((void**)&wdense_h, g_wdense_h);

    cudaFuncSetAttribute(gemm_tc_kernel,
                         cudaFuncAttributeMaxDynamicSharedMemorySize, GT_SMEM_BYTES);
    cudaFuncSetAttribute(attn_tc_kernel,
                         cudaFuncAttributeMaxDynamicSharedMemorySize, ATTN_SMEM_BYTES);

    // 0) fused fp16 conversion of all GEMM operands (one launch)
    round_all_kernel<<<2048, 256>>>((const float4*)hidden, (const float4*)w_qkv,
                                    (const float4*)w_dense, (uint2*)hidden_h,
                                    (uint2*)wqkv_h, (uint2*)wdense_h);

    // 1) QKV projection (fp16 mma.sync, f32 accum + bias)
    {
        dim3 grid(QKV_N / 128, S / 128);
        gemm_tc_kernel<<<grid, 256, GT_SMEM_BYTES>>>(hidden_h, wqkv_h, b_qkv,
                                                     mixed, S, QKV_N, H);
    }

    // 2) Rotary + tf32 pre-round of q/k/v (q pre-scaled into log2 domain)
    {
        dim3 grid(S, NH);
        rotary_kernel<<<grid, 64>>>(mixed);
    }

    // 3) Causal flash attention (1-D grid, qt-major descending, 2 CTAs/SM)
    attn_tc_kernel<<<NQT * NH, 128, ATTN_SMEM_BYTES>>>(mixed, ctxh);

    // 4) Dense projection (fp16 mma.sync)
    {
        dim3 grid(H / 128, S / 128);
        gemm_tc_kernel<<<grid, 256, GT_SMEM_BYTES>>>(ctxh, wdense_h, nullptr,
                                                     out, S, H, H);
    }
}